// round 9
// baseline (speedup 1.0000x reference)
#include <cuda_runtime.h>

#define WDIM  64
#define SDIM  512
#define C8    64
#define ROWST 516   // row-major phase stride (words)
#define FGST  132
#define PXF   132   // packed fragment stride (words)

// SMEM word offsets
#define FG_OFF  33792              // after packed X: 4*64 frags * 132
#define ATT_OFF (FG_OFF + 8448)    // 64x132
#define AX_OFF  (ATT_OFF + 4224)   // 2 x 32 frags * 132
#define RS_OFF  (AX_OFF + 8448)
#define ST_OFF  (RS_OFF + 64)
#define SM_TOT  (ST_OFF + 128)     // 55104 words = 220416 B

__device__ float g_inv_sigma;
__device__ float g_whP [262144];
__device__ float g_wsnP[262144];
__device__ float g_fgP [65536];

__device__ __forceinline__ unsigned f2tf(float f) {
    unsigned r;
    asm("cvt.rna.tf32.f32 %0, %1;" : "=r"(r) : "f"(f));
    return r;
}
__device__ __forceinline__ float rndtf(float f) { return __uint_as_float(f2tf(f)); }
__device__ __forceinline__ unsigned bits(float f) { return __float_as_uint(f); }

__device__ __forceinline__ void mma_tf32(float* c,
                                         unsigned a0, unsigned a1, unsigned a2, unsigned a3,
                                         unsigned b0, unsigned b1) {
    asm volatile(
        "mma.sync.aligned.m16n8k8.row.col.f32.tf32.tf32.f32 "
        "{%0,%1,%2,%3}, {%4,%5,%6,%7}, {%8,%9}, {%0,%1,%2,%3};\n"
        : "+f"(c[0]), "+f"(c[1]), "+f"(c[2]), "+f"(c[3])
        : "r"(a0), "r"(a1), "r"(a2), "r"(a3), "r"(b0), "r"(b1));
}

// ---- cp.async helpers -----------------------------------------------------
__device__ __forceinline__ void cpa16(float* s, const float* g) {
    unsigned sa = (unsigned)__cvta_generic_to_shared(s);
    asm volatile("cp.async.ca.shared.global [%0], [%1], 16;" :: "r"(sa), "l"(g));
}
__device__ __forceinline__ void cpa8(float* s, const float* g) {
    unsigned sa = (unsigned)__cvta_generic_to_shared(s);
    asm volatile("cp.async.ca.shared.global [%0], [%1], 8;" :: "r"(sa), "l"(g));
}
#define CP_COMMIT() asm volatile("cp.async.commit_group;")

// stage a 4096-word (16KB) k-step weight block with all 512 threads
__device__ __forceinline__ void stage4k(float* s, const float* g, int tid) {
    cpa16(s + tid * 4, g + tid * 4);
    cpa16(s + 2048 + tid * 4, g + 2048 + tid * 4);
    CP_COMMIT();
}
// stage a 1024-word (4KB) GEMM1 k-step block
__device__ __forceinline__ void stage1k(float* s, const float* g, int tid) {
    cpa8(s + tid * 2, g + tid * 2);
    CP_COMMIT();
}

// ---------------------------------------------------------------------------
__global__ __launch_bounds__(512)
void init_kernel(const float* __restrict__ wf, const float* __restrict__ wg,
                 const float* __restrict__ wh, const float* __restrict__ wsn,
                 const float* __restrict__ usn) {
    if (blockIdx.x < 512) {
        int i = blockIdx.x * 512 + threadIdx.x;
        {
            int j = i & 3, l = (i >> 2) & 31, h = (i >> 7) & 1, r = (i >> 8) & 1;
            int ng = (i >> 9) & 7, ks = i >> 12;
            int row = ks * 8 + (l & 3) + r * 4;
            int col = ng * 64 + (h * 4 + j) * 8 + (l >> 2);
            g_whP[i]  = rndtf(wh [(size_t)row * SDIM + col]);
            g_wsnP[i] = rndtf(wsn[(size_t)row * SDIM + col]);
        }
        if (i < 65536) {
            int j = i & 3, l = (i >> 2) & 31, r = (i >> 7) & 1;
            int ng = (i >> 8) & 3, ks = i >> 10;
            int row = ks * 8 + (l & 3) + r * 4;
            int col = ng * 32 + j * 8 + (l >> 2);
            g_fgP[i] = rndtf(col < 64 ? wf[(size_t)row * C8 + col]
                                      : wg[(size_t)row * C8 + col - 64]);
        }
        return;
    }
    __shared__ float us[512];
    __shared__ float vs[512];
    __shared__ float red[17];
    int tid = threadIdx.x, wid = tid >> 5, lane = tid & 31;
    us[tid] = usn[tid];
    __syncthreads();

    float q = 0.f;
    for (int rr = 0; rr < 32; rr++) {
        int row = wid * 32 + rr;
        const float4* wr = (const float4*)(wsn + (size_t)row * SDIM);
        const float4* ur = (const float4*)us;
        float s = 0.f;
        #pragma unroll
        for (int i = 0; i < 4; i++) {
            float4 w = wr[lane + i * 32], u = ur[lane + i * 32];
            s += w.x * u.x + w.y * u.y + w.z * u.z + w.w * u.w;
        }
        #pragma unroll
        for (int o = 16; o; o >>= 1) s += __shfl_xor_sync(0xffffffffu, s, o);
        if (lane == 0) { vs[row] = s; q += s * s; }
    }
    if (lane == 0) red[wid] = q;
    __syncthreads();
    if (tid == 0) {
        float z = 0.f;
        for (int i = 0; i < 16; i++) z += red[i];
        red[16] = 1.f / (sqrtf(z) + 1e-12f);
    }
    __syncthreads();
    float inv_nv = red[16];
    __syncthreads();

    float t0 = 0.f, t1 = 0.f, t2 = 0.f, t3 = 0.f;
    for (int i = 0; i < SDIM; i += 4) {
        t0 += vs[i + 0] * wsn[(size_t)(i + 0) * SDIM + tid];
        t1 += vs[i + 1] * wsn[(size_t)(i + 1) * SDIM + tid];
        t2 += vs[i + 2] * wsn[(size_t)(i + 2) * SDIM + tid];
        t3 += vs[i + 3] * wsn[(size_t)(i + 3) * SDIM + tid];
    }
    float tj = ((t0 + t1) + (t2 + t3)) * inv_nv;
    float q2 = tj * tj;
    #pragma unroll
    for (int o = 16; o; o >>= 1) q2 += __shfl_xor_sync(0xffffffffu, q2, o);
    if (lane == 0) red[wid] = q2;
    __syncthreads();
    if (tid == 0) {
        float z = 0.f;
        for (int i = 0; i < 16; i++) z += red[i];
        float nt = sqrtf(z);
        g_inv_sigma = (nt + 1e-12f) / z;
    }
}

// ---------------------------------------------------------------------------
// Staged MMA mainloop. Weights consumed from SMEM ring sb (D stages of 4096
// words), refilled via cp.async with per-iter wait_group(D-2)+barrier.
// Caller must have issued+committed stages 0..D-2 of gW before entry.
// AMODE 0: A from packed frags (Ap, FSTEP); AMODE 1: A row-major (stride ROWST).
// ---------------------------------------------------------------------------
template <int NKS, int D, int AMODE, int FSTEP>
__device__ __forceinline__ void mma_stage(float (&acc)[2][8][4],
                                          const float* __restrict__ Ap,
                                          const float* __restrict__ gW,
                                          float* sb,
                                          int mg, int ng, int g, int t,
                                          int lane, int tid) {
    #pragma unroll 2
    for (int ks = 0; ks < NKS; ks++) {
        asm volatile("cp.async.wait_group %0;" :: "n"(D - 2));
        __syncthreads();
        if (ks + D - 1 < NKS)
            stage4k(sb + ((ks + D - 1) & (D - 1)) * 4096,
                    gW + (size_t)(ks + D - 1) * 4096, tid);
        else
            CP_COMMIT();   // empty group keeps ring arithmetic exact
        const uint4* p = (const uint4*)(sb + (ks & (D - 1)) * 4096)
                       + (ng * 4) * 32 + lane;
        uint4 Bv0 = p[0];
        uint4 Bv1 = p[32];
        uint4 Bv2 = p[64];
        uint4 Bv3 = p[96];
        unsigned b0[8] = {Bv0.x, Bv0.y, Bv0.z, Bv0.w, Bv1.x, Bv1.y, Bv1.z, Bv1.w};
        unsigned b1[8] = {Bv2.x, Bv2.y, Bv2.z, Bv2.w, Bv3.x, Bv3.y, Bv3.z, Bv3.w};
        #pragma unroll
        for (int mi = 0; mi < 2; mi++) {
            unsigned a0, a1, a2, a3;
            if (AMODE == 0) {
                float4 av = ((const float4*)Ap)[(size_t)((mg * 2 + mi) * FSTEP + ks) * 33 + lane];
                a0 = bits(av.x); a1 = bits(av.y); a2 = bits(av.z); a3 = bits(av.w);
            } else {
                int r = mg * 32 + mi * 16 + g;
                int k = ks * 8;
                a0 = bits(Ap[r * ROWST + k + t]);
                a1 = bits(Ap[(r + 8) * ROWST + k + t]);
                a2 = bits(Ap[r * ROWST + k + t + 4]);
                a3 = bits(Ap[(r + 8) * ROWST + k + t + 4]);
            }
            #pragma unroll
            for (int nj = 0; nj < 8; nj++)
                mma_tf32(acc[mi][nj], a0, a1, a2, a3, b0[nj], b1[nj]);
        }
    }
}

// ---------------------------------------------------------------------------
extern __shared__ float smf[];

__global__ __launch_bounds__(512, 1)
void fused_kernel(const float* __restrict__ x,
                  const float* __restrict__ bf, const float* __restrict__ bg,
                  const float* __restrict__ bh,
                  const float* __restrict__ gamma,
                  const float* __restrict__ ln1g, const float* __restrict__ ln1b,
                  const float* __restrict__ ln2g, const float* __restrict__ ln2b,
                  float* __restrict__ out) {
    float* Xs     = smf;             // packed X (phase 1) / row-major (phase 2)
    float* FGs    = smf + FG_OFF;
    float* ATTp   = smf + ATT_OFF;
    float* AXp    = smf + AX_OFF;
    float* rowsum = smf + RS_OFF;
    float* stats  = smf + ST_OFF;

    const int tid  = threadIdx.x;
    const int wid  = tid >> 5;
    const int lane = tid & 31;
    const int g    = lane >> 2;
    const int t    = lane & 3;
    const size_t base = (size_t)blockIdx.x * (WDIM * SDIM);

    // GEMM1 weight staging ring lives in the (currently dead) AX region, D=4.
    float* sb1 = AXp;
    stage1k(sb1,        g_fgP,        tid);
    stage1k(sb1 + 1024, g_fgP + 1024, tid);
    stage1k(sb1 + 2048, g_fgP + 2048, tid);

    // ---- load X -> packed fragment layout, pre-rounded (overlaps staging) ----
    for (int i = tid; i < WDIM * SDIM / 4; i += 512) {
        float4 v = ((const float4*)(x + base))[i];
        int r = i >> 7;
        int c = (i & 127) << 2;
        int b = ((r >> 4) * 64 + (c >> 3)) * PXF + (r & 7) * 16
              + ((r >> 3) & 1) + 2 * ((c >> 2) & 1);
        Xs[b]      = rndtf(v.x);
        Xs[b + 4]  = rndtf(v.y);
        Xs[b + 8]  = rndtf(v.z);
        Xs[b + 12] = rndtf(v.w);
    }
    // (no standalone barrier: first loop iteration's wait+barrier covers X.)

    // ---- GEMM1: [F|G] = X @ [Wf|Wg] + bias  (staged weights, D=4) ----
    {
        const int mg1 = wid & 3;
        const int ng1 = wid >> 2;
        const float4* Af1 = (const float4*)Xs + (size_t)mg1 * 64 * 33 + lane;
        const int woff = (ng1 * 2) * 32 + lane;    // uint4 offset within 256-uint4 block
        float acc1[4][4];
        #pragma unroll
        for (int nj = 0; nj < 4; nj++)
            #pragma unroll
            for (int c = 0; c < 4; c++) acc1[nj][c] = 0.f;

        #pragma unroll 2
        for (int ks = 0; ks < 64; ks++) {
            asm volatile("cp.async.wait_group 2;");
            __syncthreads();
            if (ks + 3 < 64)
                stage1k(sb1 + ((ks + 3) & 3) * 1024, g_fgP + (size_t)(ks + 3) * 1024, tid);
            else
                CP_COMMIT();
            const uint4* p = (const uint4*)(sb1 + (ks & 3) * 1024) + woff;
            uint4 B0 = p[0];
            uint4 B1 = p[32];
            unsigned b0[4] = {B0.x, B0.y, B0.z, B0.w};
            unsigned b1[4] = {B1.x, B1.y, B1.z, B1.w};
            float4 av = Af1[(size_t)ks * 33];
            unsigned a0 = bits(av.x), a1 = bits(av.y), a2 = bits(av.z), a3 = bits(av.w);
            #pragma unroll
            for (int nj = 0; nj < 4; nj++)
                mma_tf32(acc1[nj], a0, a1, a2, a3, b0[nj], b1[nj]);
        }
        const int rA = mg1 * 16 + g;
        #pragma unroll
        for (int nj = 0; nj < 4; nj++) {
            int cg = ng1 * 32 + nj * 8 + 2 * t;
            float bias0 = (cg < 64) ? bf[cg] : bg[cg - 64];
            float bias1 = (cg + 1 < 64) ? bf[cg + 1] : bg[cg + 1 - 64];
            FGs[rA * FGST + cg]           = rndtf(acc1[nj][0] + bias0);
            FGs[rA * FGST + cg + 1]       = rndtf(acc1[nj][1] + bias1);
            FGs[(rA + 8) * FGST + cg]     = rndtf(acc1[nj][2] + bias0);
            FGs[(rA + 8) * FGST + cg + 1] = rndtf(acc1[nj][3] + bias1);
        }
    }
    __syncthreads();

    const int mhalf = wid >> 3;
    const int n8    = (wid & 7) * 8;
    const int fb8   = n8 >> 3;

    // ---- GEMM2: ATT = sigmoid(F @ G^T) -> packed ATTp ----
    {
        float acc2[2][4];
        #pragma unroll
        for (int mi = 0; mi < 2; mi++)
            #pragma unroll
            for (int c = 0; c < 4; c++) acc2[mi][c] = 0.f;

        #pragma unroll
        for (int k = 0; k < 64; k += 8) {
            unsigned b0 = bits(FGs[(n8 + g) * FGST + 64 + k + t]);
            unsigned b1 = bits(FGs[(n8 + g) * FGST + 64 + k + t + 4]);
            #pragma unroll
            for (int mi = 0; mi < 2; mi++) {
                int r = (mhalf * 2 + mi) * 16 + g;
                unsigned a0 = bits(FGs[r * FGST + k + t]);
                unsigned a1 = bits(FGs[(r + 8) * FGST + k + t]);
                unsigned a2 = bits(FGs[r * FGST + k + t + 4]);
                unsigned a3 = bits(FGs[(r + 8) * FGST + k + t + 4]);
                mma_tf32(acc2[mi], a0, a1, a2, a3, b0, b1);
            }
        }
        #pragma unroll
        for (int mi = 0; mi < 2; mi++) {
            int f = (mhalf * 2 + mi) * 8 + fb8;
            int w0 = f * PXF + (g * 4 + 2 * (t & 1)) * 4 + 2 * (t >> 1);
            ATTp[w0]     = rndtf(1.f / (1.f + __expf(-acc2[mi][0])));
            ATTp[w0 + 4] = rndtf(1.f / (1.f + __expf(-acc2[mi][1])));
            ATTp[w0 + 1] = rndtf(1.f / (1.f + __expf(-acc2[mi][2])));
            ATTp[w0 + 5] = rndtf(1.f / (1.f + __expf(-acc2[mi][3])));
        }
    }
    __syncthreads();     // FGs dead after this barrier -> staging may reuse it

    if (tid < 64) {
        int R = tid;
        int inner = (R & 7) * 16 + ((R >> 3) & 1);
        int frb = (R >> 4) * 8;
        float s = 0.f;
        for (int v = 0; v < 64; v++) {
            int w = (frb + (v >> 3)) * PXF + inner + (v & 3) * 4 + 2 * ((v >> 2) & 1);
            s += ATTp[w];
        }
        rowsum[R] = s;
    }

    // ---- GEMM3+4 fused: ATTN = (ATT @ X) @ Wh  (weights staged in FG, D=2) ----
    const int mg = wid & 1;
    const int ng = wid >> 1;
    float* wb4 = FGs;    // 2 x 4096-word stages (8192 <= 8448)

    float acc[2][8][4];
    #pragma unroll
    for (int mi = 0; mi < 2; mi++)
        #pragma unroll
        for (int nj = 0; nj < 8; nj++)
            #pragma unroll
            for (int c = 0; c < 4; c++) acc[mi][nj][c] = 0.f;

    for (int kc = 0; kc < 8; kc++) {
        const float* gW = g_whP + (size_t)(kc * 8) * 4096;
        // stage k-step 0 of this chunk now; latency hides under GEMM3
        stage4k(wb4, gW, tid);

        float* AXb = AXp + (kc & 1) * 4224;
        const int C3 = kc * 8 + fb8;

        float axc[2][4];
        #pragma unroll
        for (int mi = 0; mi < 2; mi++)
            #pragma unroll
            for (int c = 0; c < 4; c++) axc[mi][c] = 0.f;

        #pragma unroll
        for (int ks = 0; ks < 8; ks++) {
            int k = ks * 8;
            int wb0 = ((k >> 4) * 64 + C3) * PXF + t * 16 + (g & 3) * 4
                    + ((k >> 3) & 1) + 2 * ((g >> 2) & 1);
            unsigned b0 = bits(Xs[wb0]);
            unsigned b1 = bits(Xs[wb0 + 64]);
            #pragma unroll
            for (int mi = 0; mi < 2; mi++) {
                float4 av = ((const float4*)ATTp)[(size_t)((mhalf * 2 + mi) * 8 + ks) * 33 + lane];
                mma_tf32(axc[mi], bits(av.x), bits(av.y), bits(av.z), bits(av.w), b0, b1);
            }
        }
        #pragma unroll
        for (int mi = 0; mi < 2; mi++) {
            int f = (mhalf * 2 + mi) * 8 + fb8;
            int w0 = f * PXF + (g * 4 + 2 * (t & 1)) * 4 + 2 * (t >> 1);
            AXb[w0]     = rndtf(axc[mi][0]);
            AXb[w0 + 4] = rndtf(axc[mi][1]);
            AXb[w0 + 1] = rndtf(axc[mi][2]);
            AXb[w0 + 5] = rndtf(axc[mi][3]);
        }
        // first loop iteration's wait+barrier orders AX stores for all warps
        mma_stage<8, 2, 0, 8>(acc, AXb, gW, wb4, mg, ng, g, t, lane, tid);
    }

    // ---- epilogue 1: Xs (row-major now) = gamma*(attn + rowsum*bh) ----
    {
        float gam = gamma[0];
        #pragma unroll
        for (int mi = 0; mi < 2; mi++) {
            int r0 = mg * 32 + mi * 16 + g, r1 = r0 + 8;
            float rs0 = rowsum[r0], rs1 = rowsum[r1];
            #pragma unroll
            for (int nj = 0; nj < 8; nj++) {
                int c0 = ng * 64 + nj * 8 + 2 * t;
                float bh0 = bh[c0], bh1 = bh[c0 + 1];
                Xs[r0 * ROWST + c0]     = gam * (acc[mi][nj][0] + rs0 * bh0);
                Xs[r0 * ROWST + c0 + 1] = gam * (acc[mi][nj][1] + rs0 * bh1);
                Xs[r1 * ROWST + c0]     = gam * (acc[mi][nj][2] + rs1 * bh0);
                Xs[r1 * ROWST + c0 + 1] = gam * (acc[mi][nj][3] + rs1 * bh1);
            }
        }
    }
    __syncthreads();

    // GEMM5 weight staging ring: FG/ATT/AX all dead -> 4 stages from FG_OFF.
    // Prologue overlaps both LN1 passes.
    float* wb5 = FGs;
    stage4k(wb5,        g_wsnP,        tid);
    stage4k(wb5 + 4096, g_wsnP + 4096, tid);
    stage4k(wb5 + 8192, g_wsnP + 8192, tid);

    // ---- LN1 pass1: add residual x, stats ----
    {
        int row = tid >> 3, j0 = tid & 7;
        const float4* xr = (const float4*)(x + base + (size_t)row * SDIM);
        float4* Xr = (float4*)(Xs + row * ROWST);
        float s = 0.f, sq = 0.f;
        #pragma unroll
        for (int i = 0; i < 16; i++) {
            int c4 = j0 + i * 8;
            float4 v = Xr[c4];
            float4 xv = xr[c4];
            v.x += xv.x; v.y += xv.y; v.z += xv.z; v.w += xv.w;
            Xr[c4] = v;
            s  += (v.x + v.y) + (v.z + v.w);
            sq += (v.x * v.x + v.y * v.y) + (v.z * v.z + v.w * v.w);
        }
        #pragma unroll
        for (int o = 1; o <= 4; o <<= 1) {
            s  += __shfl_xor_sync(0xffffffffu, s, o);
            sq += __shfl_xor_sync(0xffffffffu, sq, o);
        }
        if (j0 == 0) {
            float mean = s * (1.f / SDIM);
            float var  = sq * (1.f / SDIM) - mean * mean;
            stats[row * 2]     = mean;
            stats[row * 2 + 1] = rsqrtf(var + 1e-6f);
        }
    }
    __syncthreads();
    // ---- LN1 pass2: normalize, pre-round ----
    {
        int row = tid >> 3, j0 = tid & 7;
        float mean = stats[row * 2], rstd = stats[row * 2 + 1];
        float4* Xr = (float4*)(Xs + row * ROWST);
        #pragma unroll
        for (int i = 0; i < 16; i++) {
            int c4 = j0 + i * 8;
            float4 v = Xr[c4];
            float4 gv = ((const float4*)ln1g)[c4];
            float4 bv = ((const float4*)ln1b)[c4];
            v.x = rndtf((v.x - mean) * rstd * gv.x + bv.x);
            v.y = rndtf((v.y - mean) * rstd * gv.y + bv.y);
            v.z = rndtf((v.z - mean) * rstd * gv.z + bv.z);
            v.w = rndtf((v.w - mean) * rstd * gv.w + bv.w);
            Xr[c4] = v;
        }
    }
    // (no standalone barrier: GEMM5 iter-0 wait+barrier orders LN1 writes)

    // ---- GEMM5: Y = out1 @ Wsn  (scalar A, staged weights D=4) ----
    #pragma unroll
    for (int mi = 0; mi < 2; mi++)
        #pragma unroll
        for (int nj = 0; nj < 8; nj++)
            #pragma unroll
            for (int c = 0; c < 4; c++) acc[mi][nj][c] = 0.f;

    mma_stage<64, 4, 1, 0>(acc, Xs, g_wsnP, wb5, mg, ng, g, t, lane, tid);
    __syncthreads();

    // ---- epilogue 2: relu(acc/sigma) -> Xs ----
    {
        float invsig = g_inv_sigma;
        #pragma unroll
        for (int mi = 0; mi < 2; mi++) {
            int r0 = mg * 32 + mi * 16 + g, r1 = r0 + 8;
            #pragma unroll
            for (int nj = 0; nj < 8; nj++) {
                int c0 = ng * 64 + nj * 8 + 2 * t;
                Xs[r0 * ROWST + c0]     = fmaxf(acc[mi][nj][0] * invsig, 0.f);
                Xs[r0 * ROWST + c0 + 1] = fmaxf(acc[mi][nj][1] * invsig, 0.f);
                Xs[r1 * ROWST + c0]     = fmaxf(acc[mi][nj][2] * invsig, 0.f);
                Xs[r1 * ROWST + c0 + 1] = fmaxf(acc[mi][nj][3] * invsig, 0.f);
            }
        }
    }
    __syncthreads();

    // ---- LN2 pass1 ----
    {
        int row = tid >> 3, j0 = tid & 7;
        const float4* Xr = (const float4*)(Xs + row * ROWST);
        float s = 0.f, sq = 0.f;
        #pragma unroll
        for (int i = 0; i < 16; i++) {
            float4 v = Xr[j0 + i * 8];
            s  += (v.x + v.y) + (v.z + v.w);
            sq += (v.x * v.x + v.y * v.y) + (v.z * v.z + v.w * v.w);
        }
        #pragma unroll
        for (int o = 1; o <= 4; o <<= 1) {
            s  += __shfl_xor_sync(0xffffffffu, s, o);
            sq += __shfl_xor_sync(0xffffffffu, sq, o);
        }
        if (j0 == 0) {
            float mean = s * (1.f / SDIM);
            float var  = sq * (1.f / SDIM) - mean * mean;
            stats[row * 2]     = mean;
            stats[row * 2 + 1] = rsqrtf(var + 1e-6f);
        }
    }
    __syncthreads();
    // ---- LN2 pass2 -> global out ----
    {
        int row = tid >> 3, j0 = tid & 7;
        float mean = stats[row * 2], rstd = stats[row * 2 + 1];
        const float4* Xr = (const float4*)(Xs + row * ROWST);
        float4* orow = (float4*)(out + base + (size_t)row * SDIM);
        #pragma unroll
        for (int i = 0; i < 16; i++) {
            int c4 = j0 + i * 8;
            float4 v = Xr[c4];
            float4 gv = ((const float4*)ln2g)[c4];
            float4 bv = ((const float4*)ln2b)[c4];
            v.x = (v.x - mean) * rstd * gv.x + bv.x;
            v.y = (v.y - mean) * rstd * gv.y + bv.y;
            v.z = (v.z - mean) * rstd * gv.z + bv.z;
            v.w = (v.w - mean) * rstd * gv.w + bv.w;
            orow[c4] = v;
        }
    }
}

// ---------------------------------------------------------------------------
extern "C" void kernel_launch(void* const* d_in, const int* in_sizes, int n_in,
                              void* d_out, int out_size) {
    (void)in_sizes; (void)n_in; (void)out_size;
    const float* x    = (const float*)d_in[0];
    const float* wf   = (const float*)d_in[1];
    const float* bf   = (const float*)d_in[2];
    const float* wg   = (const float*)d_in[3];
    const float* bg   = (const float*)d_in[4];
    const float* wh   = (const float*)d_in[5];
    const float* bh   = (const float*)d_in[6];
    const float* gam  = (const float*)d_in[7];
    const float* ln1g = (const float*)d_in[8];
    const float* ln1b = (const float*)d_in[9];
    const float* wsn  = (const float*)d_in[10];
    const float* usn  = (const float*)d_in[11];
    const float* ln2g = (const float*)d_in[12];
    const float* ln2b = (const float*)d_in[13];
    float* out = (float*)d_out;

    init_kernel<<<513, 512>>>(wf, wg, wh, wsn, usn);

    const int smem_bytes = SM_TOT * 4;
    cudaFuncSetAttribute(fused_kernel, cudaFuncAttributeMaxDynamicSharedMemorySize, smem_bytes);
    fused_kernel<<<1024, 512, smem_bytes>>>(x, bf, bg, bh, gam,
                                            ln1g, ln1b, ln2g, ln2b, out);
}

// round 10
// speedup vs baseline: 1.3182x; 1.3182x over previous
#include <cuda_runtime.h>

#define WDIM  64
#define SDIM  512
#define C8    64
#define ROWST 516   // row-major phase stride (words)
#define FGST  132
#define PXF   132   // packed fragment stride (words)

// SMEM word offsets
#define ATT_OFF 33792              // after packed X: 4*64 frags * 132
#define STG_OFF (ATT_OFF + 4224)   // 16384-word weight staging zone (4 x 4096)
#define FG_OFF  STG_OFF            // FG (64x132) lives in staging zone head; dead before staging starts
#define RS_OFF  (STG_OFF + 16384)
#define ST_OFF  (RS_OFF + 64)
#define BAR_OFF (ST_OFF + 128)     // 16 mbarriers * 2 words
#define SM_TOT  (BAR_OFF + 32)     // 54624 words = 218496 B

__device__ float g_inv_sigma;
__device__ __align__(16) float g_whP [262144];
__device__ __align__(16) float g_wsnP[262144];
__device__ __align__(16) float g_fgP [65536];

__device__ __forceinline__ unsigned f2tf(float f) {
    unsigned r;
    asm("cvt.rna.tf32.f32 %0, %1;" : "=r"(r) : "f"(f));
    return r;
}
__device__ __forceinline__ float rndtf(float f) { return __uint_as_float(f2tf(f)); }
__device__ __forceinline__ unsigned bits(float f) { return __float_as_uint(f); }

__device__ __forceinline__ void mma_tf32(float* c,
                                         unsigned a0, unsigned a1, unsigned a2, unsigned a3,
                                         unsigned b0, unsigned b1) {
    asm volatile(
        "mma.sync.aligned.m16n8k8.row.col.f32.tf32.tf32.f32 "
        "{%0,%1,%2,%3}, {%4,%5,%6,%7}, {%8,%9}, {%0,%1,%2,%3};\n"
        : "+f"(c[0]), "+f"(c[1]), "+f"(c[2]), "+f"(c[3])
        : "r"(a0), "r"(a1), "r"(a2), "r"(a3), "r"(b0), "r"(b1));
}

// ---- mbarrier / bulk-copy helpers ----------------------------------------
__device__ __forceinline__ void mbar_init(unsigned a, unsigned cnt) {
    asm volatile("mbarrier.init.shared.b64 [%0], %1;" :: "r"(a), "r"(cnt) : "memory");
}
__device__ __forceinline__ void mbar_arrive(unsigned a) {
    asm volatile("mbarrier.arrive.shared.b64 _, [%0];" :: "r"(a) : "memory");
}
__device__ __forceinline__ void mbar_wait(unsigned a, unsigned parity) {
    unsigned done = 0;
    while (!done) {
        asm volatile(
            "{\n\t.reg .pred p;\n\t"
            "mbarrier.try_wait.parity.acquire.cta.shared::cta.b64 p, [%1], %2, 0x989680;\n\t"
            "selp.b32 %0, 1, 0, p;\n\t}"
            : "=r"(done) : "r"(a), "r"(parity) : "memory");
    }
}
// 16KB gmem->smem bulk copy with transaction-count completion on fullb.
__device__ __forceinline__ void issue_stage(unsigned dst_s, const float* src, unsigned fullb) {
    asm volatile("mbarrier.arrive.expect_tx.shared.b64 _, [%0], %1;"
                 :: "r"(fullb), "r"(16384u) : "memory");
    asm volatile("cp.async.bulk.shared::cluster.global.mbarrier::complete_tx::bytes "
                 "[%0], [%1], %2, [%3];"
                 :: "r"(dst_s), "l"(src), "r"(16384u), "r"(fullb) : "memory");
}

// ---------------------------------------------------------------------------
__global__ __launch_bounds__(512)
void init_kernel(const float* __restrict__ wf, const float* __restrict__ wg,
                 const float* __restrict__ wh, const float* __restrict__ wsn,
                 const float* __restrict__ usn) {
    if (blockIdx.x < 512) {
        int i = blockIdx.x * 512 + threadIdx.x;
        {
            int j = i & 3, l = (i >> 2) & 31, h = (i >> 7) & 1, r = (i >> 8) & 1;
            int ng = (i >> 9) & 7, ks = i >> 12;
            int row = ks * 8 + (l & 3) + r * 4;
            int col = ng * 64 + (h * 4 + j) * 8 + (l >> 2);
            g_whP[i]  = rndtf(wh [(size_t)row * SDIM + col]);
            g_wsnP[i] = rndtf(wsn[(size_t)row * SDIM + col]);
        }
        if (i < 65536) {
            int j = i & 3, l = (i >> 2) & 31, r = (i >> 7) & 1;
            int ng = (i >> 8) & 3, ks = i >> 10;
            int row = ks * 8 + (l & 3) + r * 4;
            int col = ng * 32 + j * 8 + (l >> 2);
            g_fgP[i] = rndtf(col < 64 ? wf[(size_t)row * C8 + col]
                                      : wg[(size_t)row * C8 + col - 64]);
        }
        return;
    }
    __shared__ float us[512];
    __shared__ float vs[512];
    __shared__ float red[17];
    int tid = threadIdx.x, wid = tid >> 5, lane = tid & 31;
    us[tid] = usn[tid];
    __syncthreads();

    float q = 0.f;
    for (int rr = 0; rr < 32; rr++) {
        int row = wid * 32 + rr;
        const float4* wr = (const float4*)(wsn + (size_t)row * SDIM);
        const float4* ur = (const float4*)us;
        float s = 0.f;
        #pragma unroll
        for (int i = 0; i < 4; i++) {
            float4 w = wr[lane + i * 32], u = ur[lane + i * 32];
            s += w.x * u.x + w.y * u.y + w.z * u.z + w.w * u.w;
        }
        #pragma unroll
        for (int o = 16; o; o >>= 1) s += __shfl_xor_sync(0xffffffffu, s, o);
        if (lane == 0) { vs[row] = s; q += s * s; }
    }
    if (lane == 0) red[wid] = q;
    __syncthreads();
    if (tid == 0) {
        float z = 0.f;
        for (int i = 0; i < 16; i++) z += red[i];
        red[16] = 1.f / (sqrtf(z) + 1e-12f);
    }
    __syncthreads();
    float inv_nv = red[16];
    __syncthreads();

    float t0 = 0.f, t1 = 0.f, t2 = 0.f, t3 = 0.f;
    for (int i = 0; i < SDIM; i += 4) {
        t0 += vs[i + 0] * wsn[(size_t)(i + 0) * SDIM + tid];
        t1 += vs[i + 1] * wsn[(size_t)(i + 1) * SDIM + tid];
        t2 += vs[i + 2] * wsn[(size_t)(i + 2) * SDIM + tid];
        t3 += vs[i + 3] * wsn[(size_t)(i + 3) * SDIM + tid];
    }
    float tj = ((t0 + t1) + (t2 + t3)) * inv_nv;
    float q2 = tj * tj;
    #pragma unroll
    for (int o = 16; o; o >>= 1) q2 += __shfl_xor_sync(0xffffffffu, q2, o);
    if (lane == 0) red[wid] = q2;
    __syncthreads();
    if (tid == 0) {
        float z = 0.f;
        for (int i = 0; i < 16; i++) z += red[i];
        float nt = sqrtf(z);
        g_inv_sigma = (nt + 1e-12f) / z;
    }
}

// ---------------------------------------------------------------------------
extern __shared__ float smf[];

__global__ __launch_bounds__(512, 1)
void fused_kernel(const float* __restrict__ x,
                  const float* __restrict__ bf, const float* __restrict__ bg,
                  const float* __restrict__ bh,
                  const float* __restrict__ gamma,
                  const float* __restrict__ ln1g, const float* __restrict__ ln1b,
                  const float* __restrict__ ln2g, const float* __restrict__ ln2b,
                  float* __restrict__ out) {
    float* Xs     = smf;             // packed X -> packed AX -> row-major out1
    float* ATTp   = smf + ATT_OFF;   // packed ATT (32 frags)
    float* FGs    = smf + FG_OFF;    // 64x132 row-major (dies before staging starts)
    float* STG    = smf + STG_OFF;   // 4 x 4096-word weight stages
    float* rowsum = smf + RS_OFF;
    float* stats  = smf + ST_OFF;

    const int tid  = threadIdx.x;
    const int wid  = tid >> 5;
    const int lane = tid & 31;
    const int g    = lane >> 2;
    const int t    = lane & 3;
    const size_t base = (size_t)blockIdx.x * (WDIM * SDIM);

    const unsigned barb = (unsigned)__cvta_generic_to_shared(smf + BAR_OFF);
    const unsigned full4  = barb;        // 4 x 8B
    const unsigned empty4 = barb + 32;
    const unsigned full5  = barb + 64;
    const unsigned empty5 = barb + 96;
    const unsigned stg_s  = (unsigned)__cvta_generic_to_shared(STG);

    if (tid == 0) {
        #pragma unroll
        for (int s = 0; s < 4; s++) {
            mbar_init(full4  + s * 8, 1);
            mbar_init(empty4 + s * 8, 16);
            mbar_init(full5  + s * 8, 1);
            mbar_init(empty5 + s * 8, 16);
        }
    }

    // ---- load X -> packed fragment layout, pre-rounded ----
    for (int i = tid; i < WDIM * SDIM / 4; i += 512) {
        float4 v = ((const float4*)(x + base))[i];
        int r = i >> 7;
        int c = (i & 127) << 2;
        int b = ((r >> 4) * 64 + (c >> 3)) * PXF + (r & 7) * 16
              + ((r >> 3) & 1) + 2 * ((c >> 2) & 1);
        Xs[b]      = rndtf(v.x);
        Xs[b + 4]  = rndtf(v.y);
        Xs[b + 8]  = rndtf(v.z);
        Xs[b + 12] = rndtf(v.w);
    }
    __syncthreads();   // X + mbarrier init visible

    // ---- GEMM1: [F|G] = X @ [Wf|Wg] + bias  (direct LDG weights, frag A) ----
    {
        const int mg1 = wid & 3;
        const int ng1 = wid >> 2;
        const float4* Af1 = (const float4*)Xs + (size_t)mg1 * 64 * 33 + lane;
        const uint4* fgp = (const uint4*)g_fgP + (size_t)(ng1 * 2) * 32 + lane;
        float acc1[4][4];
        #pragma unroll
        for (int nj = 0; nj < 4; nj++)
            #pragma unroll
            for (int c = 0; c < 4; c++) acc1[nj][c] = 0.f;

        #pragma unroll 2
        for (int ks = 0; ks < 64; ks++) {
            const uint4* p = fgp + (size_t)ks * 256;
            uint4 B0 = p[0];
            uint4 B1 = p[32];
            unsigned b0[4] = {B0.x, B0.y, B0.z, B0.w};
            unsigned b1[4] = {B1.x, B1.y, B1.z, B1.w};
            float4 av = Af1[(size_t)ks * 33];
            unsigned a0 = bits(av.x), a1 = bits(av.y), a2 = bits(av.z), a3 = bits(av.w);
            #pragma unroll
            for (int nj = 0; nj < 4; nj++)
                mma_tf32(acc1[nj], a0, a1, a2, a3, b0[nj], b1[nj]);
        }
        const int rA = mg1 * 16 + g;
        #pragma unroll
        for (int nj = 0; nj < 4; nj++) {
            int cg = ng1 * 32 + nj * 8 + 2 * t;
            float bias0 = (cg < 64) ? bf[cg] : bg[cg - 64];
            float bias1 = (cg + 1 < 64) ? bf[cg + 1] : bg[cg + 1 - 64];
            FGs[rA * FGST + cg]           = rndtf(acc1[nj][0] + bias0);
            FGs[rA * FGST + cg + 1]       = rndtf(acc1[nj][1] + bias1);
            FGs[(rA + 8) * FGST + cg]     = rndtf(acc1[nj][2] + bias0);
            FGs[(rA + 8) * FGST + cg + 1] = rndtf(acc1[nj][3] + bias1);
        }
    }
    __syncthreads();

    const int mhalf = wid >> 3;
    const int n8    = (wid & 7) * 8;
    const int fb8   = n8 >> 3;

    // ---- GEMM2: ATT = sigmoid(F @ G^T) -> packed ATTp ----
    {
        float acc2[2][4];
        #pragma unroll
        for (int mi = 0; mi < 2; mi++)
            #pragma unroll
            for (int c = 0; c < 4; c++) acc2[mi][c] = 0.f;

        #pragma unroll
        for (int k = 0; k < 64; k += 8) {
            unsigned b0 = bits(FGs[(n8 + g) * FGST + 64 + k + t]);
            unsigned b1 = bits(FGs[(n8 + g) * FGST + 64 + k + t + 4]);
            #pragma unroll
            for (int mi = 0; mi < 2; mi++) {
                int r = (mhalf * 2 + mi) * 16 + g;
                unsigned a0 = bits(FGs[r * FGST + k + t]);
                unsigned a1 = bits(FGs[(r + 8) * FGST + k + t]);
                unsigned a2 = bits(FGs[r * FGST + k + t + 4]);
                unsigned a3 = bits(FGs[(r + 8) * FGST + k + t + 4]);
                mma_tf32(acc2[mi], a0, a1, a2, a3, b0, b1);
            }
        }
        #pragma unroll
        for (int mi = 0; mi < 2; mi++) {
            int f = (mhalf * 2 + mi) * 8 + fb8;
            int w0 = f * PXF + (g * 4 + 2 * (t & 1)) * 4 + 2 * (t >> 1);
            ATTp[w0]     = rndtf(1.f / (1.f + __expf(-acc2[mi][0])));
            ATTp[w0 + 4] = rndtf(1.f / (1.f + __expf(-acc2[mi][1])));
            ATTp[w0 + 1] = rndtf(1.f / (1.f + __expf(-acc2[mi][2])));
            ATTp[w0 + 5] = rndtf(1.f / (1.f + __expf(-acc2[mi][3])));
        }
    }
    __syncthreads();     // FG dead from here -> staging zone free

    // GEMM4 staging prologue: 4 stages of Wh land while GEMM3 computes.
    if (tid == 0) {
        #pragma unroll
        for (int j = 0; j < 4; j++)
            issue_stage(stg_s + j * 16384u, g_whP + (size_t)j * 4096, full4 + j * 8);
    }

    if (tid < 64) {
        int R = tid;
        int inner = (R & 7) * 16 + ((R >> 3) & 1);
        int frb = (R >> 4) * 8;
        float s = 0.f;
        for (int v = 0; v < 64; v++) {
            int w = (frb + (v >> 3)) * PXF + inner + (v & 3) * 4 + 2 * ((v >> 2) & 1);
            s += ATTp[w];
        }
        rowsum[R] = s;
    }

    // ---- GEMM3: AX = ATT @ X, chunk-by-chunk, overwriting X in place ----
    for (int kc = 0; kc < 8; kc++) {
        const int C3 = kc * 8 + fb8;

        float axc[2][4];
        #pragma unroll
        for (int mi = 0; mi < 2; mi++)
            #pragma unroll
            for (int c = 0; c < 4; c++) axc[mi][c] = 0.f;

        #pragma unroll
        for (int ks = 0; ks < 8; ks++) {
            int k = ks * 8;
            int wb0 = ((k >> 4) * 64 + C3) * PXF + t * 16 + (g & 3) * 4
                    + ((k >> 3) & 1) + 2 * ((g >> 2) & 1);
            unsigned b0 = bits(Xs[wb0]);
            unsigned b1 = bits(Xs[wb0 + 64]);
            #pragma unroll
            for (int mi = 0; mi < 2; mi++) {
                float4 av = ((const float4*)ATTp)[(size_t)((mhalf * 2 + mi) * 8 + ks) * 33 + lane];
                mma_tf32(axc[mi], bits(av.x), bits(av.y), bits(av.z), bits(av.w), b0, b1);
            }
        }
        __syncthreads();   // all reads of X chunk kc complete
        #pragma unroll
        for (int mi = 0; mi < 2; mi++) {
            int f = ((mhalf * 2 + mi) * 64) + C3;      // full-width packed AX
            int w0 = f * PXF + (g * 4 + 2 * (t & 1)) * 4 + 2 * (t >> 1);
            Xs[w0]     = rndtf(axc[mi][0]);
            Xs[w0 + 4] = rndtf(axc[mi][1]);
            Xs[w0 + 1] = rndtf(axc[mi][2]);
            Xs[w0 + 5] = rndtf(axc[mi][3]);
        }
    }
    __syncthreads();       // full packed AX visible to all warps

    // ---- GEMM4: ATTN = AX @ Wh  (streaming, mbarrier-staged weights) ----
    const int mg = wid & 1;
    const int ng = wid >> 1;

    float acc[2][8][4];
    #pragma unroll
    for (int mi = 0; mi < 2; mi++)
        #pragma unroll
        for (int nj = 0; nj < 8; nj++)
            #pragma unroll
            for (int c = 0; c < 4; c++) acc[mi][nj][c] = 0.f;

    for (int i = 0; i < 64; i++) {
        const int slot = i & 3;
        const unsigned par = (unsigned)((i >> 2) & 1);
        mbar_wait(full4 + slot * 8, par);
        const uint4* p = (const uint4*)(STG + slot * 4096) + ng * 128 + lane;
        uint4 Bv0 = p[0];
        uint4 Bv1 = p[32];
        uint4 Bv2 = p[64];
        uint4 Bv3 = p[96];
        unsigned b0[8] = {Bv0.x, Bv0.y, Bv0.z, Bv0.w, Bv1.x, Bv1.y, Bv1.z, Bv1.w};
        unsigned b1[8] = {Bv2.x, Bv2.y, Bv2.z, Bv2.w, Bv3.x, Bv3.y, Bv3.z, Bv3.w};
        #pragma unroll
        for (int mi = 0; mi < 2; mi++) {
            float4 av = ((const float4*)Xs)[(size_t)((mg * 2 + mi) * 64 + i) * 33 + lane];
            unsigned a0 = bits(av.x), a1 = bits(av.y), a2 = bits(av.z), a3 = bits(av.w);
            #pragma unroll
            for (int nj = 0; nj < 8; nj++)
                mma_tf32(acc[mi][nj], a0, a1, a2, a3, b0[nj], b1[nj]);
        }
        if (lane == 0) mbar_arrive(empty4 + slot * 8);
        if (tid == 0 && i < 60) {
            mbar_wait(empty4 + slot * 8, par);
            issue_stage(stg_s + slot * 16384u, g_whP + (size_t)(i + 4) * 4096, full4 + slot * 8);
        }
    }
    __syncthreads();       // all stage reads + AX reads done

    // GEMM5 staging prologue: Wsn stages land while epilogue1 + LN1 run.
    if (tid == 0) {
        #pragma unroll
        for (int j = 0; j < 4; j++)
            issue_stage(stg_s + j * 16384u, g_wsnP + (size_t)j * 4096, full5 + j * 8);
    }

    // ---- epilogue 1: Xs (row-major now) = gamma*(attn + rowsum*bh) ----
    {
        float gam = gamma[0];
        #pragma unroll
        for (int mi = 0; mi < 2; mi++) {
            int r0 = mg * 32 + mi * 16 + g, r1 = r0 + 8;
            float rs0 = rowsum[r0], rs1 = rowsum[r1];
            #pragma unroll
            for (int nj = 0; nj < 8; nj++) {
                int c0 = ng * 64 + nj * 8 + 2 * t;
                float bh0 = bh[c0], bh1 = bh[c0 + 1];
                Xs[r0 * ROWST + c0]     = gam * (acc[mi][nj][0] + rs0 * bh0);
                Xs[r0 * ROWST + c0 + 1] = gam * (acc[mi][nj][1] + rs0 * bh1);
                Xs[r1 * ROWST + c0]     = gam * (acc[mi][nj][2] + rs1 * bh0);
                Xs[r1 * ROWST + c0 + 1] = gam * (acc[mi][nj][3] + rs1 * bh1);
            }
        }
    }
    __syncthreads();

    // ---- LN1 pass1: add residual x (re-read), stats ----
    {
        int row = tid >> 3, j0 = tid & 7;
        const float4* xr = (const float4*)(x + base + (size_t)row * SDIM);
        float4* Xr = (float4*)(Xs + row * ROWST);
        float s = 0.f, sq = 0.f;
        #pragma unroll
        for (int i = 0; i < 16; i++) {
            int c4 = j0 + i * 8;
            float4 v = Xr[c4];
            float4 xv = xr[c4];
            v.x += xv.x; v.y += xv.y; v.z += xv.z; v.w += xv.w;
            Xr[c4] = v;
            s  += (v.x + v.y) + (v.z + v.w);
            sq += (v.x * v.x + v.y * v.y) + (v.z * v.z + v.w * v.w);
        }
        #pragma unroll
        for (int o = 1; o <= 4; o <<= 1) {
            s  += __shfl_xor_sync(0xffffffffu, s, o);
            sq += __shfl_xor_sync(0xffffffffu, sq, o);
        }
        if (j0 == 0) {
            float mean = s * (1.f / SDIM);
            float var  = sq * (1.f / SDIM) - mean * mean;
            stats[row * 2]     = mean;
            stats[row * 2 + 1] = rsqrtf(var + 1e-6f);
        }
    }
    __syncthreads();
    // ---- LN1 pass2: normalize, pre-round ----
    {
        int row = tid >> 3, j0 = tid & 7;
        float mean = stats[row * 2], rstd = stats[row * 2 + 1];
        float4* Xr = (float4*)(Xs + row * ROWST);
        #pragma unroll
        for (int i = 0; i < 16; i++) {
            int c4 = j0 + i * 8;
            float4 v = Xr[c4];
            float4 gv = ((const float4*)ln1g)[c4];
            float4 bv = ((const float4*)ln1b)[c4];
            v.x = rndtf((v.x - mean) * rstd * gv.x + bv.x);
            v.y = rndtf((v.y - mean) * rstd * gv.y + bv.y);
            v.z = rndtf((v.z - mean) * rstd * gv.z + bv.z);
            v.w = rndtf((v.w - mean) * rstd * gv.w + bv.w);
            Xr[c4] = v;
        }
    }
    __syncthreads();       // out1 visible to all warps

    // ---- GEMM5: Y = out1 @ Wsn  (streaming, mbarrier-staged weights) ----
    #pragma unroll
    for (int mi = 0; mi < 2; mi++)
        #pragma unroll
        for (int nj = 0; nj < 8; nj++)
            #pragma unroll
            for (int c = 0; c < 4; c++) acc[mi][nj][c] = 0.f;

    for (int i = 0; i < 64; i++) {
        const int slot = i & 3;
        const unsigned par = (unsigned)((i >> 2) & 1);
        mbar_wait(full5 + slot * 8, par);
        const uint4* p = (const uint4*)(STG + slot * 4096) + ng * 128 + lane;
        uint4 Bv0 = p[0];
        uint4 Bv1 = p[32];
        uint4 Bv2 = p[64];
        uint4 Bv3 = p[96];
        unsigned b0[8] = {Bv0.x, Bv0.y, Bv0.z, Bv0.w, Bv1.x, Bv1.y, Bv1.z, Bv1.w};
        unsigned b1[8] = {Bv2.x, Bv2.y, Bv2.z, Bv2.w, Bv3.x, Bv3.y, Bv3.z, Bv3.w};
        int k = i * 8;
        #pragma unroll
        for (int mi = 0; mi < 2; mi++) {
            int r = mg * 32 + mi * 16 + g;
            unsigned a0 = bits(Xs[r * ROWST + k + t]);
            unsigned a1 = bits(Xs[(r + 8) * ROWST + k + t]);
            unsigned a2 = bits(Xs[r * ROWST + k + t + 4]);
            unsigned a3 = bits(Xs[(r + 8) * ROWST + k + t + 4]);
            #pragma unroll
            for (int nj = 0; nj < 8; nj++)
                mma_tf32(acc[mi][nj], a0, a1, a2, a3, b0[nj], b1[nj]);
        }
        if (lane == 0) mbar_arrive(empty5 + slot * 8);
        if (tid == 0 && i < 60) {
            mbar_wait(empty5 + slot * 8, par);
            issue_stage(stg_s + slot * 16384u, g_wsnP + (size_t)(i + 4) * 4096, full5 + slot * 8);
        }
    }
    __syncthreads();       // all warps done reading out1 before overwrite

    // ---- epilogue 2: relu(acc/sigma) -> Xs ----
    {
        float invsig = g_inv_sigma;
        #pragma unroll
        for (int mi = 0; mi < 2; mi++) {
            int r0 = mg * 32 + mi * 16 + g, r1 = r0 + 8;
            #pragma unroll
            for (int nj = 0; nj < 8; nj++) {
                int c0 = ng * 64 + nj * 8 + 2 * t;
                Xs[r0 * ROWST + c0]     = fmaxf(acc[mi][nj][0] * invsig, 0.f);
                Xs[r0 * ROWST + c0 + 1] = fmaxf(acc[mi][nj][1] * invsig, 0.f);
                Xs[r1 * ROWST + c0]     = fmaxf(acc[mi][nj][2] * invsig, 0.f);
                Xs[r1 * ROWST + c0 + 1] = fmaxf(acc[mi][nj][3] * invsig, 0.f);
            }
        }
    }
    __syncthreads();

    // ---- LN2 pass1 ----
    {
        int row = tid >> 3, j0 = tid & 7;
        const float4* Xr = (const float4*)(Xs + row * ROWST);
        float s = 0.f, sq = 0.f;
        #pragma unroll
        for (int i = 0; i < 16; i++) {
            float4 v = Xr[j0 + i * 8];
            s  += (v.x + v.y) + (v.z + v.w);
            sq += (v.x * v.x + v.y * v.y) + (v.z * v.z + v.w * v.w);
        }
        #pragma unroll
        for (int o = 1; o <= 4; o <<= 1) {
            s  += __shfl_xor_sync(0xffffffffu, s, o);
            sq += __shfl_xor_sync(0xffffffffu, sq, o);
        }
        if (j0 == 0) {
            float mean = s * (1.f / SDIM);
            float var  = sq * (1.f / SDIM) - mean * mean;
            stats[row * 2]     = mean;
            stats[row * 2 + 1] = rsqrtf(var + 1e-6f);
        }
    }
    __syncthreads();
    // ---- LN2 pass2 -> global out ----
    {
        int row = tid >> 3, j0 = tid & 7;
        float mean = stats[row * 2], rstd = stats[row * 2 + 1];
        const float4* Xr = (const float4*)(Xs + row * ROWST);
        float4* orow = (float4*)(out + base + (size_t)row * SDIM);
        #pragma unroll
        for (int i = 0; i < 16; i++) {
            int c4 = j0 + i * 8;
            float4 v = Xr[c4];
            float4 gv = ((const float4*)ln2g)[c4];
            float4 bv = ((const float4*)ln2b)[c4];
            v.x = (v.x - mean) * rstd * gv.x + bv.x;
            v.y = (v.y - mean) * rstd * gv.y + bv.y;
            v.z = (v.z - mean) * rstd * gv.z + bv.z;
            v.w = (v.w - mean) * rstd * gv.w + bv.w;
            orow[c4] = v;
        }
    }
}

// ---------------------------------------------------------------------------
extern "C" void kernel_launch(void* const* d_in, const int* in_sizes, int n_in,
                              void* d_out, int out_size) {
    (void)in_sizes; (void)n_in; (void)out_size;
    const float* x    = (const float*)d_in[0];
    const float* wf   = (const float*)d_in[1];
    const float* bf   = (const float*)d_in[2];
    const float* wg   = (const float*)d_in[3];
    const float* bg   = (const float*)d_in[4];
    const float* wh   = (const float*)d_in[5];
    const float* bh   = (const float*)d_in[6];
    const float* gam  = (const float*)d_in[7];
    const float* ln1g = (const float*)d_in[8];
    const float* ln1b = (const float*)d_in[9];
    const float* wsn  = (const float*)d_in[10];
    const float* usn  = (const float*)d_in[11];
    const float* ln2g = (const float*)d_in[12];
    const float* ln2b = (const float*)d_in[13];
    float* out = (float*)d_out;

    init_kernel<<<513, 512>>>(wf, wg, wh, wsn, usn);

    const int smem_bytes = SM_TOT * 4;
    cudaFuncSetAttribute(fused_kernel, cudaFuncAttributeMaxDynamicSharedMemorySize, smem_bytes);
    fused_kernel<<<1024, 512, smem_bytes>>>(x, bf, bg, bh, gam,
                                            ln1g, ln1b, ln2g, ln2b, out);
}